// round 14
// baseline (speedup 1.0000x reference)
#include <cuda_runtime.h>
#include <cuda_bf16.h>
#include <math.h>
#include <stdint.h>

// ---------------------------------------------------------------------------
// Problem constants
// ---------------------------------------------------------------------------
#define BATCH    2
#define SEQ      2048
#define DIM      1024
#define NHEAD    16
#define HDIM     64
#define HIDDEN   4096
#define TOKENS   (BATCH * SEQ)          // 4096
#define QKV_DIM  (3 * DIM)              // 3072
#define LN_EPS   1e-5f

// ---------------------------------------------------------------------------
// Scratch buffers (bf16 activations where they only feed tensor ops;
// residual stream fp32)
// ---------------------------------------------------------------------------
__device__ __nv_bfloat16 g_xn [TOKENS * DIM];
__device__ __nv_bfloat16 g_qkv[TOKENS * QKV_DIM];
__device__ __nv_bfloat16 g_att[TOKENS * DIM];
__device__ float         g_x1 [TOKENS * DIM];
__device__ __nv_bfloat16 g_h  [TOKENS * HIDDEN];
__device__ __nv_bfloat16 g_wq[QKV_DIM * DIM];
__device__ __nv_bfloat16 g_wp[DIM * DIM];
__device__ __nv_bfloat16 g_w1[HIDDEN * DIM];
__device__ __nv_bfloat16 g_w2[DIM * HIDDEN];

// ---------------------------------------------------------------------------
// Helpers
// ---------------------------------------------------------------------------
__device__ __forceinline__ uint32_t smem_u32(const void* p)
{
    return (uint32_t)__cvta_generic_to_shared(p);
}

__device__ __forceinline__ void mma_bf16(float c[4], const uint32_t a[4],
                                         uint32_t b0, uint32_t b1)
{
    asm volatile(
        "mma.sync.aligned.m16n8k16.row.col.f32.bf16.bf16.f32 "
        "{%0,%1,%2,%3}, {%4,%5,%6,%7}, {%8,%9}, {%0,%1,%2,%3};"
        : "+f"(c[0]), "+f"(c[1]), "+f"(c[2]), "+f"(c[3])
        : "r"(a[0]), "r"(a[1]), "r"(a[2]), "r"(a[3]), "r"(b0), "r"(b1));
}

// ---------------------------------------------------------------------------
// Weight conversion fp32 -> bf16
// ---------------------------------------------------------------------------
__global__ void cvt_bf16_kernel(const float* __restrict__ in,
                                __nv_bfloat16* __restrict__ out, int n)
{
    int i = (blockIdx.x * 256 + threadIdx.x) * 4;
    if (i < n) {
        float4 v = *(const float4*)(in + i);
        __nv_bfloat162 lo = __floats2bfloat162_rn(v.x, v.y);
        __nv_bfloat162 hi = __floats2bfloat162_rn(v.z, v.w);
        uint2 pk;
        pk.x = *(uint32_t*)&lo;
        pk.y = *(uint32_t*)&hi;
        *(uint2*)(out + i) = pk;
    }
}

// ---------------------------------------------------------------------------
// LayerNorm: fp32 in, bf16 out
// ---------------------------------------------------------------------------
__global__ void ln_kernel(const float* __restrict__ in,
                          const float* __restrict__ gamma,
                          const float* __restrict__ beta,
                          __nv_bfloat16* __restrict__ out)
{
    int row = blockIdx.x;
    int tid = threadIdx.x;               // 256
    const float4* rp = (const float4*)(in + (size_t)row * DIM);
    float4 v = rp[tid];

    float s  = v.x + v.y + v.z + v.w;
    float s2 = v.x*v.x + v.y*v.y + v.z*v.z + v.w*v.w;

    __shared__ float rs[256];
    __shared__ float rq[256];
    rs[tid] = s; rq[tid] = s2;
    __syncthreads();
    #pragma unroll
    for (int o = 128; o > 0; o >>= 1) {
        if (tid < o) { rs[tid] += rs[tid + o]; rq[tid] += rq[tid + o]; }
        __syncthreads();
    }
    float mu  = rs[0] * (1.0f / DIM);
    float var = rq[0] * (1.0f / DIM) - mu * mu;
    float rstd = rsqrtf(var + LN_EPS);

    float4 g4 = ((const float4*)gamma)[tid];
    float4 b4 = ((const float4*)beta)[tid];
    __nv_bfloat162 lo = __floats2bfloat162_rn(
        (v.x - mu) * rstd * g4.x + b4.x, (v.y - mu) * rstd * g4.y + b4.y);
    __nv_bfloat162 hi = __floats2bfloat162_rn(
        (v.z - mu) * rstd * g4.z + b4.z, (v.w - mu) * rstd * g4.w + b4.w);
    uint2 pk;
    pk.x = *(uint32_t*)&lo;
    pk.y = *(uint32_t*)&hi;
    *(uint2*)(out + (size_t)row * DIM + tid * 4) = pk;
}

// ---------------------------------------------------------------------------
// BF16 mma.sync GEMM, 3-stage cp.async pipeline (BK=32), scalar fragment
// loads. C[M,N] = A[M,K] @ W[N,K]^T + bias (+ epilogue).
//   BM=BN=128, 8 warps (2m x 4n), warp tile 64x32, m16n8k16.
//   GSPAD=56 elems (112B rows): 16B-aligned cp.async dst, conflict-free
//   fragment banks ((28*gid+tig) mod 32 all distinct). 2 CTAs/SM (86KB).
// ---------------------------------------------------------------------------
#define EPI_BIAS 0   // bias, bf16 out (qkv)
#define EPI_GELU 1   // bias+gelu, bf16 out (ff1)
#define EPI_RES  2   // bias+residual, fp32 out (proj, ff2)
#define GBK   32
#define GSPAD 56
#define GEMM_SMEM (3 * 2 * 128 * GSPAD * sizeof(uint16_t))   // 86016 B

template<int EPI>
__global__ __launch_bounds__(256, 2)
void gemm_bf16_kernel(const __nv_bfloat16* __restrict__ A,
                      const __nv_bfloat16* __restrict__ W,
                      const float* __restrict__ bias,
                      const float* __restrict__ res,
                      void* __restrict__ Cv,
                      int M, int N, int K)
{
    extern __shared__ __align__(16) uint16_t smem_b[];
    // stage s: A at smem_b + s*2*128*GSPAD, B at +128*GSPAD
    int t    = threadIdx.x;
    int lane = t & 31;
    int wid  = t >> 5;
    int gid  = lane >> 2;
    int tig  = lane & 3;
    int warpM = (wid >> 2) * 64;
    int warpN = (wid & 3) * 32;
    int m0 = blockIdx.y * 128;
    int n0 = blockIdx.x * 128;

    int lrow = t >> 2;            // 0..63
    int lc   = (t & 3) * 8;       // bf16 elem 0,8,16,24 (16B chunks)

    float acc[4][4][4];
    #pragma unroll
    for (int im = 0; im < 4; im++)
        #pragma unroll
        for (int jn = 0; jn < 4; jn++)
            #pragma unroll
            for (int r = 0; r < 4; r++) acc[im][jn][r] = 0.0f;

    const __nv_bfloat16* agbase = A + (size_t)(m0 + lrow) * K + lc;
    const __nv_bfloat16* bgbase = W + (size_t)(n0 + lrow) * K + lc;

    auto issue = [&](int kt, int buf) {
        const __nv_bfloat16* ag = agbase + kt * GBK;
        const __nv_bfloat16* bg = bgbase + kt * GBK;
        uint16_t* Asp = smem_b + buf * 2 * 128 * GSPAD;
        uint16_t* Bsp = Asp + 128 * GSPAD;
        #pragma unroll
        for (int p = 0; p < 2; p++) {
            uint32_t da = smem_u32(Asp + (lrow + p * 64) * GSPAD + lc);
            asm volatile("cp.async.cg.shared.global [%0], [%1], 16;\n"
                         :: "r"(da), "l"(ag + (size_t)p * 64 * K));
            uint32_t db = smem_u32(Bsp + (lrow + p * 64) * GSPAD + lc);
            asm volatile("cp.async.cg.shared.global [%0], [%1], 16;\n"
                         :: "r"(db), "l"(bg + (size_t)p * 64 * K));
        }
        asm volatile("cp.async.commit_group;\n");
    };

    auto compute = [&](int buf) {
        uint16_t* Asp = smem_b + buf * 2 * 128 * GSPAD;
        uint16_t* Bsp = Asp + 128 * GSPAD;
        #pragma unroll
        for (int ks = 0; ks < 2; ks++) {
            int kb = ks * 16;
            uint32_t af[4][4];
            #pragma unroll
            for (int im = 0; im < 4; im++) {
                const uint16_t* ap0 = Asp + (warpM + im * 16 + gid) * GSPAD + kb + tig * 2;
                const uint16_t* ap1 = ap0 + 8 * GSPAD;
                af[im][0] = *(const uint32_t*)(ap0);
                af[im][1] = *(const uint32_t*)(ap1);
                af[im][2] = *(const uint32_t*)(ap0 + 8);
                af[im][3] = *(const uint32_t*)(ap1 + 8);
            }
            uint32_t bf[4][2];
            #pragma unroll
            for (int jn = 0; jn < 4; jn++) {
                const uint16_t* bp = Bsp + (warpN + jn * 8 + gid) * GSPAD + kb + tig * 2;
                bf[jn][0] = *(const uint32_t*)(bp);
                bf[jn][1] = *(const uint32_t*)(bp + 8);
            }
            #pragma unroll
            for (int im = 0; im < 4; im++)
                #pragma unroll
                for (int jn = 0; jn < 4; jn++)
                    mma_bf16(acc[im][jn], af[im], bf[jn][0], bf[jn][1]);
        }
    };

    int nt = K / GBK;
    issue(0, 0);
    issue(1, 1);
    // buffer rotation mod 3; one __syncthreads per iteration.
    int b0i = 0, b1i = 1, b2i = 2;
    for (int i = 0; i < nt; i++) {
        if (i == nt - 1) {
            asm volatile("cp.async.wait_group 0;\n");
        } else {
            asm volatile("cp.async.wait_group 1;\n");
        }
        __syncthreads();
        if (i + 2 < nt) issue(i + 2, b2i);
        compute(b0i);
        int tmp = b0i; b0i = b1i; b1i = b2i; b2i = tmp;
    }

    // Epilogue. m16n8: c0,c1 -> row gid, cols tig*2,+1; c2,c3 -> row gid+8.
    #pragma unroll
    for (int im = 0; im < 4; im++) {
        #pragma unroll
        for (int jn = 0; jn < 4; jn++) {
            int col = n0 + warpN + jn * 8 + tig * 2;
            float b0v = bias[col], b1v = bias[col + 1];
            #pragma unroll
            for (int half = 0; half < 2; half++) {
                int row = m0 + warpM + im * 16 + gid + half * 8;
                float v0 = acc[im][jn][half * 2 + 0] + b0v;
                float v1 = acc[im][jn][half * 2 + 1] + b1v;
                if (EPI == EPI_GELU) {
                    v0 = 0.5f * v0 * (1.0f + erff(v0 * 0.70710678118654752f));
                    v1 = 0.5f * v1 * (1.0f + erff(v1 * 0.70710678118654752f));
                }
                if (EPI == EPI_RES) {
                    float2 rr = *(const float2*)(res + (size_t)row * N + col);
                    float2 o2; o2.x = v0 + rr.x; o2.y = v1 + rr.y;
                    *(float2*)((float*)Cv + (size_t)row * N + col) = o2;
                } else {
                    __nv_bfloat162 pk = __floats2bfloat162_rn(v0, v1);
                    *(uint32_t*)((__nv_bfloat16*)Cv + (size_t)row * N + col) =
                        *(uint32_t*)&pk;
                }
            }
        }
    }
}

// ---------------------------------------------------------------------------
// BF16 tensor-core flash attention (unchanged from R11, 622us baseline).
// ---------------------------------------------------------------------------
#define SPAD  72
#define FTC_SMEM ((128 + 64 + 64 + 128) * SPAD * sizeof(uint16_t))   // 55296 B

__global__ __launch_bounds__(256, 2)
void flash_tc_kernel(const __nv_bfloat16* __restrict__ qkv,
                     __nv_bfloat16* __restrict__ out)
{
    extern __shared__ __align__(16) uint16_t smem_b[];
    uint16_t* Qs = smem_b;                   // [128][SPAD]
    uint16_t* Ks = Qs + 128 * SPAD;          // [64][SPAD]
    uint16_t* Vt = Ks + 64 * SPAD;           // [64][SPAD]
    uint16_t* Ps = Vt + 64 * SPAD;           // [128][SPAD]

    int QT = gridDim.x - 1 - blockIdx.x;
    int h  = blockIdx.y;
    int b  = blockIdx.z;
    int t  = threadIdx.x;
    int lane = t & 31;
    int wid  = t >> 5;
    int gid  = lane >> 2;
    int tig  = lane & 3;
    int warpRow = wid * 16;

    const __nv_bfloat16* base = qkv + (size_t)b * SEQ * QKV_DIM;

    {
        int r  = t >> 1;                    // 0..127
        int d0 = (t & 1) * 32;
        const __nv_bfloat16* qrow = base + (size_t)(QT * 128 + r) * QKV_DIM + h * HDIM + d0;
        __nv_bfloat162 sc = __floats2bfloat162_rn(0.125f, 0.125f);
        uint16_t* dst = Qs + r * SPAD + d0;
        #pragma unroll
        for (int u = 0; u < 4; u++) {
            uint4 raw = ((const uint4*)qrow)[u];
            __nv_bfloat162* pr = (__nv_bfloat162*)&raw;
            #pragma unroll
            for (int e = 0; e < 4; e++) pr[e] = __hmul2(pr[e], sc);
            ((uint4*)dst)[u] = raw;
        }
    }

    float m0 = -1e30f, m1 = -1e30f, l0 = 0.0f, l1 = 0.0f;
    float oacc[8][4];
    #pragma unroll
    for (int dn = 0; dn < 8; dn++)
        #pragma unroll
        for (int r = 0; r < 4; r++) oacc[dn][r] = 0.0f;

    int q0 = QT * 128 + warpRow + gid;
    int ktmax = QT * 2 + 1;

    for (int kt = 0; kt <= ktmax; kt++) {
        __syncthreads();
        {
            int r  = t >> 2;                // 0..63
            int c0 = (t & 3) * 16;
            const __nv_bfloat16* krow = base + (size_t)(kt * 64 + r) * QKV_DIM + DIM + h * HDIM + c0;
            uint16_t* kdst = Ks + r * SPAD + c0;
            ((uint4*)kdst)[0] = ((const uint4*)krow)[0];
            ((uint4*)kdst)[1] = ((const uint4*)krow)[1];

            int j  = t & 63;
            int d0 = (t >> 6) * 16;
            const __nv_bfloat16* vrow = base + (size_t)(kt * 64 + j) * QKV_DIM + 2 * DIM + h * HDIM + d0;
            #pragma unroll
            for (int u = 0; u < 2; u++) {
                uint4 raw = ((const uint4*)vrow)[u];
                uint16_t* rw = (uint16_t*)&raw;
                #pragma unroll
                for (int e = 0; e < 8; e++)
                    Vt[(d0 + u * 8 + e) * SPAD + j] = rw[e];
            }
        }
        __syncthreads();

        float sacc[8][4];
        #pragma unroll
        for (int jn = 0; jn < 8; jn++)
            #pragma unroll
            for (int r = 0; r < 4; r++) sacc[jn][r] = 0.0f;

        #pragma unroll
        for (int ks = 0; ks < 4; ks++) {
            int kb = ks * 16;
            uint32_t af[4];
            {
                const uint16_t* ap0 = Qs + (warpRow + gid) * SPAD + kb + tig * 2;
                const uint16_t* ap1 = ap0 + 8 * SPAD;
                af[0] = *(const uint32_t*)(ap0);
                af[1] = *(const uint32_t*)(ap1);
                af[2] = *(const uint32_t*)(ap0 + 8);
                af[3] = *(const uint32_t*)(ap1 + 8);
            }
            #pragma unroll
            for (int jn = 0; jn < 8; jn++) {
                const uint16_t* bp = Ks + (jn * 8 + gid) * SPAD + kb + tig * 2;
                mma_bf16(sacc[jn], af, *(const uint32_t*)(bp),
                                       *(const uint32_t*)(bp + 8));
            }
        }

        if (kt * 64 + 63 > QT * 128 + warpRow) {
            #pragma unroll
            for (int jn = 0; jn < 8; jn++) {
                int jg = kt * 64 + jn * 8 + tig * 2;
                if (jg     > q0    ) sacc[jn][0] = -1e30f;
                if (jg + 1 > q0    ) sacc[jn][1] = -1e30f;
                if (jg     > q0 + 8) sacc[jn][2] = -1e30f;
                if (jg + 1 > q0 + 8) sacc[jn][3] = -1e30f;
            }
        }

        float rm0 = -1e30f, rm1 = -1e30f;
        #pragma unroll
        for (int jn = 0; jn < 8; jn++) {
            rm0 = fmaxf(rm0, fmaxf(sacc[jn][0], sacc[jn][1]));
            rm1 = fmaxf(rm1, fmaxf(sacc[jn][2], sacc[jn][3]));
        }
        rm0 = fmaxf(rm0, __shfl_xor_sync(0xffffffffu, rm0, 1));
        rm0 = fmaxf(rm0, __shfl_xor_sync(0xffffffffu, rm0, 2));
        rm1 = fmaxf(rm1, __shfl_xor_sync(0xffffffffu, rm1, 1));
        rm1 = fmaxf(rm1, __shfl_xor_sync(0xffffffffu, rm1, 2));

        float mn0 = fmaxf(m0, rm0);
        float mn1 = fmaxf(m1, rm1);
        float a0 = __expf(m0 - mn0);
        float a1 = __expf(m1 - mn1);

        float rs0 = 0.0f, rs1 = 0.0f;
        #pragma unroll
        for (int jn = 0; jn < 8; jn++) {
            float p0 = __expf(sacc[jn][0] - mn0);
            float p1 = __expf(sacc[jn][1] - mn0);
            float p2 = __expf(sacc[jn][2] - mn1);
            float p3 = __expf(sacc[jn][3] - mn1);
            rs0 += p0 + p1;
            rs1 += p2 + p3;
            int col = jn * 8 + tig * 2;
            __nv_bfloat162 w0 = __floats2bfloat162_rn(p0, p1);
            __nv_bfloat162 w1 = __floats2bfloat162_rn(p2, p3);
            *(uint32_t*)(Ps + (warpRow + gid    ) * SPAD + col) = *(uint32_t*)&w0;
            *(uint32_t*)(Ps + (warpRow + gid + 8) * SPAD + col) = *(uint32_t*)&w1;
        }
        rs0 += __shfl_xor_sync(0xffffffffu, rs0, 1);
        rs0 += __shfl_xor_sync(0xffffffffu, rs0, 2);
        rs1 += __shfl_xor_sync(0xffffffffu, rs1, 1);
        rs1 += __shfl_xor_sync(0xffffffffu, rs1, 2);

        l0 = l0 * a0 + rs0; m0 = mn0;
        l1 = l1 * a1 + rs1; m1 = mn1;
        #pragma unroll
        for (int dn = 0; dn < 8; dn++) {
            oacc[dn][0] *= a0; oacc[dn][1] *= a0;
            oacc[dn][2] *= a1; oacc[dn][3] *= a1;
        }
        __syncwarp();

        #pragma unroll
        for (int ks = 0; ks < 4; ks++) {
            int kb = ks * 16;
            uint32_t af[4];
            {
                const uint16_t* ap0 = Ps + (warpRow + gid) * SPAD + kb + tig * 2;
                const uint16_t* ap1 = ap0 + 8 * SPAD;
                af[0] = *(const uint32_t*)(ap0);
                af[1] = *(const uint32_t*)(ap1);
                af[2] = *(const uint32_t*)(ap0 + 8);
                af[3] = *(const uint32_t*)(ap1 + 8);
            }
            #pragma unroll
            for (int dn = 0; dn < 8; dn++) {
                const uint16_t* bp = Vt + (dn * 8 + gid) * SPAD + kb + tig * 2;
                mma_bf16(oacc[dn], af, *(const uint32_t*)(bp),
                                       *(const uint32_t*)(bp + 8));
            }
        }
        __syncwarp();
    }

    float inv0 = 1.0f / l0;
    float inv1 = 1.0f / l1;
    __nv_bfloat16* orow0 = out + ((size_t)(b * SEQ) + q0    ) * DIM + h * HDIM;
    __nv_bfloat16* orow1 = out + ((size_t)(b * SEQ) + q0 + 8) * DIM + h * HDIM;
    #pragma unroll
    for (int dn = 0; dn < 8; dn++) {
        int col = dn * 8 + tig * 2;
        __nv_bfloat162 w0 = __floats2bfloat162_rn(oacc[dn][0] * inv0, oacc[dn][1] * inv0);
        __nv_bfloat162 w1 = __floats2bfloat162_rn(oacc[dn][2] * inv1, oacc[dn][3] * inv1);
        *(uint32_t*)(orow0 + col) = *(uint32_t*)&w0;
        *(uint32_t*)(orow1 + col) = *(uint32_t*)&w1;
    }
}

// ---------------------------------------------------------------------------
// Launcher
// ---------------------------------------------------------------------------
extern "C" void kernel_launch(void* const* d_in, const int* in_sizes, int n_in,
                              void* d_out, int out_size)
{
    const float* x      = (const float*)d_in[0];
    const float* qkv_w  = (const float*)d_in[1];
    const float* qkv_b  = (const float*)d_in[2];
    const float* proj_w = (const float*)d_in[3];
    const float* proj_b = (const float*)d_in[4];
    const float* ff1_w  = (const float*)d_in[5];
    const float* ff1_b  = (const float*)d_in[6];
    const float* ff2_w  = (const float*)d_in[7];
    const float* ff2_b  = (const float*)d_in[8];
    const float* ln1_g  = (const float*)d_in[9];
    const float* ln1_b  = (const float*)d_in[10];
    const float* ln2_g  = (const float*)d_in[11];
    const float* ln2_b  = (const float*)d_in[12];
    float* out = (float*)d_out;

    __nv_bfloat16 *xn, *qkv, *att, *hbuf, *wq, *wp, *w1, *w2;
    float *x1;
    cudaGetSymbolAddress((void**)&xn,   g_xn);
    cudaGetSymbolAddress((void**)&qkv,  g_qkv);
    cudaGetSymbolAddress((void**)&att,  g_att);
    cudaGetSymbolAddress((void**)&x1,   g_x1);
    cudaGetSymbolAddress((void**)&hbuf, g_h);
    cudaGetSymbolAddress((void**)&wq,   g_wq);
    cudaGetSymbolAddress((void**)&wp,   g_wp);
    cudaGetSymbolAddress((void**)&w1,   g_w1);
    cudaGetSymbolAddress((void**)&w2,   g_w2);

    cudaFuncSetAttribute(flash_tc_kernel,
                         cudaFuncAttributeMaxDynamicSharedMemorySize, FTC_SMEM);
    cudaFuncSetAttribute(gemm_bf16_kernel<EPI_BIAS>,
                         cudaFuncAttributeMaxDynamicSharedMemorySize, GEMM_SMEM);
    cudaFuncSetAttribute(gemm_bf16_kernel<EPI_GELU>,
                         cudaFuncAttributeMaxDynamicSharedMemorySize, GEMM_SMEM);
    cudaFuncSetAttribute(gemm_bf16_kernel<EPI_RES>,
                         cudaFuncAttributeMaxDynamicSharedMemorySize, GEMM_SMEM);

    // 0. Convert weights to bf16
    cvt_bf16_kernel<<<(QKV_DIM * DIM / 4 + 255) / 256, 256>>>(qkv_w, wq, QKV_DIM * DIM);
    cvt_bf16_kernel<<<(DIM * DIM / 4 + 255) / 256, 256>>>(proj_w, wp, DIM * DIM);
    cvt_bf16_kernel<<<(HIDDEN * DIM / 4 + 255) / 256, 256>>>(ff1_w, w1, HIDDEN * DIM);
    cvt_bf16_kernel<<<(DIM * HIDDEN / 4 + 255) / 256, 256>>>(ff2_w, w2, DIM * HIDDEN);

    // 1. LN1 -> bf16
    ln_kernel<<<TOKENS, 256>>>(x, ln1_g, ln1_b, xn);

    // 2. QKV projection -> bf16
    {
        dim3 grid(QKV_DIM / 128, TOKENS / 128);
        gemm_bf16_kernel<EPI_BIAS><<<grid, 256, GEMM_SMEM>>>(xn, wq, qkv_b, nullptr, qkv,
                                                             TOKENS, QKV_DIM, DIM);
    }

    // 3. Flash attention -> bf16
    {
        dim3 grid(SEQ / 128, NHEAD, BATCH);
        flash_tc_kernel<<<grid, 256, FTC_SMEM>>>(qkv, att);
    }

    // 4. proj + residual -> fp32 x1
    {
        dim3 grid(DIM / 128, TOKENS / 128);
        gemm_bf16_kernel<EPI_RES><<<grid, 256, GEMM_SMEM>>>(att, wp, proj_b, x, x1,
                                                            TOKENS, DIM, DIM);
    }

    // 5. LN2 -> bf16
    ln_kernel<<<TOKENS, 256>>>(x1, ln2_g, ln2_b, xn);

    // 6. FF1 + GELU -> bf16
    {
        dim3 grid(HIDDEN / 128, TOKENS / 128);
        gemm_bf16_kernel<EPI_GELU><<<grid, 256, GEMM_SMEM>>>(xn, w1, ff1_b, nullptr, hbuf,
                                                             TOKENS, HIDDEN, DIM);
    }

    // 7. FF2 + residual -> fp32 d_out
    {
        dim3 grid(DIM / 128, TOKENS / 128);
        gemm_bf16_kernel<EPI_RES><<<grid, 256, GEMM_SMEM>>>(hbuf, w2, ff2_b, x1, out,
                                                            TOKENS, DIM, HIDDEN);
    }
}

// round 16
// speedup vs baseline: 1.0850x; 1.0850x over previous
#include <cuda_runtime.h>
#include <cuda_bf16.h>
#include <math.h>
#include <stdint.h>

// ---------------------------------------------------------------------------
// Problem constants
// ---------------------------------------------------------------------------
#define BATCH    2
#define SEQ      2048
#define DIM      1024
#define NHEAD    16
#define HDIM     64
#define HIDDEN   4096
#define TOKENS   (BATCH * SEQ)          // 4096
#define QKV_DIM  (3 * DIM)              // 3072
#define LN_EPS   1e-5f

// ---------------------------------------------------------------------------
// Scratch buffers
// ---------------------------------------------------------------------------
__device__ __nv_bfloat16 g_xn [TOKENS * DIM];
__device__ __nv_bfloat16 g_qkv[TOKENS * QKV_DIM];
__device__ __nv_bfloat16 g_att[TOKENS * DIM];
__device__ float         g_x1 [TOKENS * DIM];
__device__ __nv_bfloat16 g_h  [TOKENS * HIDDEN];
__device__ __nv_bfloat16 g_wq[QKV_DIM * DIM];
__device__ __nv_bfloat16 g_wp[DIM * DIM];
__device__ __nv_bfloat16 g_w1[HIDDEN * DIM];
__device__ __nv_bfloat16 g_w2[DIM * HIDDEN];

// ---------------------------------------------------------------------------
// Helpers
// ---------------------------------------------------------------------------
__device__ __forceinline__ uint32_t smem_u32(const void* p)
{
    return (uint32_t)__cvta_generic_to_shared(p);
}

__device__ __forceinline__ void mma_bf16(float c[4], const uint32_t a[4],
                                         uint32_t b0, uint32_t b1)
{
    asm volatile(
        "mma.sync.aligned.m16n8k16.row.col.f32.bf16.bf16.f32 "
        "{%0,%1,%2,%3}, {%4,%5,%6,%7}, {%8,%9}, {%0,%1,%2,%3};"
        : "+f"(c[0]), "+f"(c[1]), "+f"(c[2]), "+f"(c[3])
        : "r"(a[0]), "r"(a[1]), "r"(a[2]), "r"(a[3]), "r"(b0), "r"(b1));
}

// ---------------------------------------------------------------------------
// Fused weight conversion fp32 -> bf16 (all four weights, one launch).
// ---------------------------------------------------------------------------
__global__ void cvt_all_kernel(const float* __restrict__ s0, __nv_bfloat16* d0, int n0,
                               const float* __restrict__ s1, __nv_bfloat16* d1, int n1,
                               const float* __restrict__ s2, __nv_bfloat16* d2, int n2,
                               const float* __restrict__ s3, __nv_bfloat16* d3, int n3)
{
    long i = ((long)blockIdx.x * 256 + threadIdx.x) * 4;
    const float* s; __nv_bfloat16* d;
    if (i < n0)                { s = s0;                    d = d0;                    }
    else if (i < n0 + n1)      { s = s1 - n0;               d = d1 - n0;               }
    else if (i < n0 + n1 + n2) { s = s2 - n0 - n1;          d = d2 - n0 - n1;          }
    else if (i < n0 + n1 + n2 + n3) { s = s3 - n0 - n1 - n2; d = d3 - n0 - n1 - n2;    }
    else return;
    float4 v = *(const float4*)(s + i);
    __nv_bfloat162 lo = __floats2bfloat162_rn(v.x, v.y);
    __nv_bfloat162 hi = __floats2bfloat162_rn(v.z, v.w);
    uint2 pk;
    pk.x = *(uint32_t*)&lo;
    pk.y = *(uint32_t*)&hi;
    *(uint2*)(d + i) = pk;
}

// ---------------------------------------------------------------------------
// LayerNorm: fp32 in, bf16 out
// ---------------------------------------------------------------------------
__global__ void ln_kernel(const float* __restrict__ in,
                          const float* __restrict__ gamma,
                          const float* __restrict__ beta,
                          __nv_bfloat16* __restrict__ out)
{
    int row = blockIdx.x;
    int tid = threadIdx.x;               // 256
    const float4* rp = (const float4*)(in + (size_t)row * DIM);
    float4 v = rp[tid];

    float s  = v.x + v.y + v.z + v.w;
    float s2 = v.x*v.x + v.y*v.y + v.z*v.z + v.w*v.w;

    __shared__ float rs[256];
    __shared__ float rq[256];
    rs[tid] = s; rq[tid] = s2;
    __syncthreads();
    #pragma unroll
    for (int o = 128; o > 0; o >>= 1) {
        if (tid < o) { rs[tid] += rs[tid + o]; rq[tid] += rq[tid + o]; }
        __syncthreads();
    }
    float mu  = rs[0] * (1.0f / DIM);
    float var = rq[0] * (1.0f / DIM) - mu * mu;
    float rstd = rsqrtf(var + LN_EPS);

    float4 g4 = ((const float4*)gamma)[tid];
    float4 b4 = ((const float4*)beta)[tid];
    __nv_bfloat162 lo = __floats2bfloat162_rn(
        (v.x - mu) * rstd * g4.x + b4.x, (v.y - mu) * rstd * g4.y + b4.y);
    __nv_bfloat162 hi = __floats2bfloat162_rn(
        (v.z - mu) * rstd * g4.z + b4.z, (v.w - mu) * rstd * g4.w + b4.w);
    uint2 pk;
    pk.x = *(uint32_t*)&lo;
    pk.y = *(uint32_t*)&hi;
    *(uint2*)(out + (size_t)row * DIM + tid * 4) = pk;
}

// ---------------------------------------------------------------------------
// BF16 mma.sync GEMM — EXACT R11 configuration (622.7us baseline):
//   BM=BN=128, BK=64, 2-stage cp.async, scalar fragment loads, 2 CTAs/SM.
// ---------------------------------------------------------------------------
#define EPI_BIAS 0
#define EPI_GELU 1
#define EPI_RES  2
#define GBK   64
#define SPAD  72
#define GEMM_SMEM (2 * 2 * 128 * SPAD * sizeof(uint16_t))   // 73728 B

template<int EPI>
__global__ __launch_bounds__(256, 2)
void gemm_bf16_kernel(const __nv_bfloat16* __restrict__ A,
                      const __nv_bfloat16* __restrict__ W,
                      const float* __restrict__ bias,
                      const float* __restrict__ res,
                      void* __restrict__ Cv,
                      int M, int N, int K)
{
    extern __shared__ __align__(16) uint16_t smem_b[];
    uint16_t* AsB = smem_b;                      // [2][128][SPAD]
    uint16_t* BsB = smem_b + 2 * 128 * SPAD;

    int t    = threadIdx.x;
    int lane = t & 31;
    int wid  = t >> 5;
    int gid  = lane >> 2;
    int tig  = lane & 3;
    int warpM = (wid >> 2) * 64;
    int warpN = (wid & 3) * 32;
    int m0 = blockIdx.y * 128;
    int n0 = blockIdx.x * 128;

    int lrow = t >> 3;            // 0..31
    int lk   = (t & 7) * 8;       // bf16 idx 0..56

    float acc[4][4][4];
    #pragma unroll
    for (int im = 0; im < 4; im++)
        #pragma unroll
        for (int jn = 0; jn < 4; jn++)
            #pragma unroll
            for (int r = 0; r < 4; r++) acc[im][jn][r] = 0.0f;

    const __nv_bfloat16* agbase = A + (size_t)(m0 + lrow) * K + lk;
    const __nv_bfloat16* bgbase = W + (size_t)(n0 + lrow) * K + lk;

    auto issue = [&](int kt, int buf) {
        const __nv_bfloat16* ag = agbase + kt * GBK;
        const __nv_bfloat16* bg = bgbase + kt * GBK;
        uint16_t* Asp = AsB + buf * 128 * SPAD;
        uint16_t* Bsp = BsB + buf * 128 * SPAD;
        #pragma unroll
        for (int p = 0; p < 4; p++) {
            uint32_t da = smem_u32(Asp + (lrow + p * 32) * SPAD + lk);
            asm volatile("cp.async.cg.shared.global [%0], [%1], 16;\n"
                         :: "r"(da), "l"(ag + (size_t)p * 32 * K));
            uint32_t db = smem_u32(Bsp + (lrow + p * 32) * SPAD + lk);
            asm volatile("cp.async.cg.shared.global [%0], [%1], 16;\n"
                         :: "r"(db), "l"(bg + (size_t)p * 32 * K));
        }
        asm volatile("cp.async.commit_group;\n");
    };

    auto compute = [&](int buf) {
        uint16_t* Asp = AsB + buf * 128 * SPAD;
        uint16_t* Bsp = BsB + buf * 128 * SPAD;
        #pragma unroll
        for (int ks = 0; ks < 4; ks++) {
            int kb = ks * 16;
            uint32_t af[4][4];
            #pragma unroll
            for (int im = 0; im < 4; im++) {
                const uint16_t* ap0 = Asp + (warpM + im * 16 + gid) * SPAD + kb + tig * 2;
                const uint16_t* ap1 = ap0 + 8 * SPAD;
                af[im][0] = *(const uint32_t*)(ap0);
                af[im][1] = *(const uint32_t*)(ap1);
                af[im][2] = *(const uint32_t*)(ap0 + 8);
                af[im][3] = *(const uint32_t*)(ap1 + 8);
            }
            uint32_t bf[4][2];
            #pragma unroll
            for (int jn = 0; jn < 4; jn++) {
                const uint16_t* bp = Bsp + (warpN + jn * 8 + gid) * SPAD + kb + tig * 2;
                bf[jn][0] = *(const uint32_t*)(bp);
                bf[jn][1] = *(const uint32_t*)(bp + 8);
            }
            #pragma unroll
            for (int im = 0; im < 4; im++)
                #pragma unroll
                for (int jn = 0; jn < 4; jn++)
                    mma_bf16(acc[im][jn], af[im], bf[jn][0], bf[jn][1]);
        }
    };

    int nt = K / GBK;
    issue(0, 0);
    for (int i = 0; i < nt; i++) {
        if (i + 1 < nt) {
            issue(i + 1, (i + 1) & 1);
            asm volatile("cp.async.wait_group 1;\n");
        } else {
            asm volatile("cp.async.wait_group 0;\n");
        }
        __syncthreads();
        compute(i & 1);
        __syncthreads();
    }

    #pragma unroll
    for (int im = 0; im < 4; im++) {
        #pragma unroll
        for (int jn = 0; jn < 4; jn++) {
            int col = n0 + warpN + jn * 8 + tig * 2;
            float b0v = bias[col], b1v = bias[col + 1];
            #pragma unroll
            for (int half = 0; half < 2; half++) {
                int row = m0 + warpM + im * 16 + gid + half * 8;
                float v0 = acc[im][jn][half * 2 + 0] + b0v;
                float v1 = acc[im][jn][half * 2 + 1] + b1v;
                if (EPI == EPI_GELU) {
                    v0 = 0.5f * v0 * (1.0f + erff(v0 * 0.70710678118654752f));
                    v1 = 0.5f * v1 * (1.0f + erff(v1 * 0.70710678118654752f));
                }
                if (EPI == EPI_RES) {
                    float2 rr = *(const float2*)(res + (size_t)row * N + col);
                    float2 o2; o2.x = v0 + rr.x; o2.y = v1 + rr.y;
                    *(float2*)((float*)Cv + (size_t)row * N + col) = o2;
                } else {
                    __nv_bfloat162 pk = __floats2bfloat162_rn(v0, v1);
                    *(uint32_t*)((__nv_bfloat16*)Cv + (size_t)row * N + col) =
                        *(uint32_t*)&pk;
                }
            }
        }
    }
}

// ---------------------------------------------------------------------------
// BF16 flash attention with double-buffered K/V tiles.
//   K loads via cp.async; V transpose via LDG+STS issued one tile ahead.
// Smem (bf16): Qs[128][72], Ks[2][64][72], Vt[2][64][72], Ps[128][72]
// ---------------------------------------------------------------------------
#define FTC_SMEM ((128 + 2 * 64 + 2 * 64 + 128) * SPAD * sizeof(uint16_t))  // 73728 B

__global__ __launch_bounds__(256, 2)
void flash_tc_kernel(const __nv_bfloat16* __restrict__ qkv,
                     __nv_bfloat16* __restrict__ out)
{
    extern __shared__ __align__(16) uint16_t smem_b[];
    uint16_t* Qs  = smem_b;                    // [128][SPAD]
    uint16_t* KsB = Qs + 128 * SPAD;           // [2][64][SPAD]
    uint16_t* VtB = KsB + 2 * 64 * SPAD;       // [2][64][SPAD]
    uint16_t* Ps  = VtB + 2 * 64 * SPAD;       // [128][SPAD]

    int QT = gridDim.x - 1 - blockIdx.x;
    int h  = blockIdx.y;
    int b  = blockIdx.z;
    int t  = threadIdx.x;
    int lane = t & 31;
    int wid  = t >> 5;
    int gid  = lane >> 2;
    int tig  = lane & 3;
    int warpRow = wid * 16;

    const __nv_bfloat16* base = qkv + (size_t)b * SEQ * QKV_DIM;

    // Load tile kt's K (cp.async) and V (LDG + transpose STS) into buffer buf.
    auto load_tile = [&](int kt, int buf) {
        int r  = t >> 2;                // 0..63
        int c0 = (t & 3) * 16;          // 0,16,32,48 bf16 elems
        const __nv_bfloat16* krow = base + (size_t)(kt * 64 + r) * QKV_DIM + DIM + h * HDIM + c0;
        uint16_t* kd = KsB + buf * 64 * SPAD + r * SPAD + c0;
        asm volatile("cp.async.cg.shared.global [%0], [%1], 16;\n"
                     :: "r"(smem_u32(kd)), "l"(krow));
        asm volatile("cp.async.cg.shared.global [%0], [%1], 16;\n"
                     :: "r"(smem_u32(kd + 8)), "l"(krow + 8));

        int j  = t & 63;
        int d0 = (t >> 6) * 16;
        const __nv_bfloat16* vrow = base + (size_t)(kt * 64 + j) * QKV_DIM + 2 * DIM + h * HDIM + d0;
        uint16_t* vt = VtB + buf * 64 * SPAD;
        #pragma unroll
        for (int u = 0; u < 2; u++) {
            uint4 raw = ((const uint4*)vrow)[u];
            uint16_t* rw = (uint16_t*)&raw;
            #pragma unroll
            for (int e = 0; e < 8; e++)
                vt[(d0 + u * 8 + e) * SPAD + j] = rw[e];
        }
        asm volatile("cp.async.commit_group;\n");
    };

    // ---- load Q tile (128 x 64), scale by 0.125 (exact in bf16) ----
    {
        int r  = t >> 1;
        int d0 = (t & 1) * 32;
        const __nv_bfloat16* qrow = base + (size_t)(QT * 128 + r) * QKV_DIM + h * HDIM + d0;
        __nv_bfloat162 sc = __floats2bfloat162_rn(0.125f, 0.125f);
        uint16_t* dst = Qs + r * SPAD + d0;
        #pragma unroll
        for (int u = 0; u < 4; u++) {
            uint4 raw = ((const uint4*)qrow)[u];
            __nv_bfloat162* pr = (__nv_bfloat162*)&raw;
            #pragma unroll
            for (int e = 0; e < 4; e++) pr[e] = __hmul2(pr[e], sc);
            ((uint4*)dst)[u] = raw;
        }
    }

    float m0 = -1e30f, m1 = -1e30f, l0 = 0.0f, l1 = 0.0f;
    float oacc[8][4];
    #pragma unroll
    for (int dn = 0; dn < 8; dn++)
        #pragma unroll
        for (int r = 0; r < 4; r++) oacc[dn][r] = 0.0f;

    int q0 = QT * 128 + warpRow + gid;
    int ktmax = QT * 2 + 1;

    load_tile(0, 0);

    for (int kt = 0; kt <= ktmax; kt++) {
        int bb = kt & 1;
        if (kt < ktmax) {
            load_tile(kt + 1, bb ^ 1);
            asm volatile("cp.async.wait_group 1;\n");
        } else {
            asm volatile("cp.async.wait_group 0;\n");
        }
        __syncthreads();

        const uint16_t* Ks = KsB + bb * 64 * SPAD;
        const uint16_t* Vt = VtB + bb * 64 * SPAD;

        // ---- S = Q K^T : warp computes 16 x 64 ----
        float sacc[8][4];
        #pragma unroll
        for (int jn = 0; jn < 8; jn++)
            #pragma unroll
            for (int r = 0; r < 4; r++) sacc[jn][r] = 0.0f;

        #pragma unroll
        for (int ks = 0; ks < 4; ks++) {
            int kb = ks * 16;
            uint32_t af[4];
            {
                const uint16_t* ap0 = Qs + (warpRow + gid) * SPAD + kb + tig * 2;
                const uint16_t* ap1 = ap0 + 8 * SPAD;
                af[0] = *(const uint32_t*)(ap0);
                af[1] = *(const uint32_t*)(ap1);
                af[2] = *(const uint32_t*)(ap0 + 8);
                af[3] = *(const uint32_t*)(ap1 + 8);
            }
            #pragma unroll
            for (int jn = 0; jn < 8; jn++) {
                const uint16_t* bp = Ks + (jn * 8 + gid) * SPAD + kb + tig * 2;
                mma_bf16(sacc[jn], af, *(const uint32_t*)(bp),
                                       *(const uint32_t*)(bp + 8));
            }
        }

        // ---- causal mask ----
        if (kt * 64 + 63 > QT * 128 + warpRow) {
            #pragma unroll
            for (int jn = 0; jn < 8; jn++) {
                int jg = kt * 64 + jn * 8 + tig * 2;
                if (jg     > q0    ) sacc[jn][0] = -1e30f;
                if (jg + 1 > q0    ) sacc[jn][1] = -1e30f;
                if (jg     > q0 + 8) sacc[jn][2] = -1e30f;
                if (jg + 1 > q0 + 8) sacc[jn][3] = -1e30f;
            }
        }

        // ---- online softmax ----
        float rm0 = -1e30f, rm1 = -1e30f;
        #pragma unroll
        for (int jn = 0; jn < 8; jn++) {
            rm0 = fmaxf(rm0, fmaxf(sacc[jn][0], sacc[jn][1]));
            rm1 = fmaxf(rm1, fmaxf(sacc[jn][2], sacc[jn][3]));
        }
        rm0 = fmaxf(rm0, __shfl_xor_sync(0xffffffffu, rm0, 1));
        rm0 = fmaxf(rm0, __shfl_xor_sync(0xffffffffu, rm0, 2));
        rm1 = fmaxf(rm1, __shfl_xor_sync(0xffffffffu, rm1, 1));
        rm1 = fmaxf(rm1, __shfl_xor_sync(0xffffffffu, rm1, 2));

        float mn0 = fmaxf(m0, rm0);
        float mn1 = fmaxf(m1, rm1);
        float a0 = __expf(m0 - mn0);
        float a1 = __expf(m1 - mn1);

        float rs0 = 0.0f, rs1 = 0.0f;
        #pragma unroll
        for (int jn = 0; jn < 8; jn++) {
            float p0 = __expf(sacc[jn][0] - mn0);
            float p1 = __expf(sacc[jn][1] - mn0);
            float p2 = __expf(sacc[jn][2] - mn1);
            float p3 = __expf(sacc[jn][3] - mn1);
            rs0 += p0 + p1;
            rs1 += p2 + p3;
            int col = jn * 8 + tig * 2;
            __nv_bfloat162 w0 = __floats2bfloat162_rn(p0, p1);
            __nv_bfloat162 w1 = __floats2bfloat162_rn(p2, p3);
            *(uint32_t*)(Ps + (warpRow + gid    ) * SPAD + col) = *(uint32_t*)&w0;
            *(uint32_t*)(Ps + (warpRow + gid + 8) * SPAD + col) = *(uint32_t*)&w1;
        }
        rs0 += __shfl_xor_sync(0xffffffffu, rs0, 1);
        rs0 += __shfl_xor_sync(0xffffffffu, rs0, 2);
        rs1 += __shfl_xor_sync(0xffffffffu, rs1, 1);
        rs1 += __shfl_xor_sync(0xffffffffu, rs1, 2);

        l0 = l0 * a0 + rs0; m0 = mn0;
        l1 = l1 * a1 + rs1; m1 = mn1;
        #pragma unroll
        for (int dn = 0; dn < 8; dn++) {
            oacc[dn][0] *= a0; oacc[dn][1] *= a0;
            oacc[dn][2] *= a1; oacc[dn][3] *= a1;
        }
        __syncwarp();

        // ---- O += P V ----
        #pragma unroll
        for (int ks = 0; ks < 4; ks++) {
            int kb = ks * 16;
            uint32_t af[4];
            {
                const uint16_t* ap0 = Ps + (warpRow + gid) * SPAD + kb + tig * 2;
                const uint16_t* ap1 = ap0 + 8 * SPAD;
                af[0] = *(const uint32_t*)(ap0);
                af[1] = *(const uint32_t*)(ap1);
                af[2] = *(const uint32_t*)(ap0 + 8);
                af[3] = *(const uint32_t*)(ap1 + 8);
            }
            #pragma unroll
            for (int dn = 0; dn < 8; dn++) {
                const uint16_t* bp = Vt + (dn * 8 + gid) * SPAD + kb + tig * 2;
                mma_bf16(oacc[dn], af, *(const uint32_t*)(bp),
                                       *(const uint32_t*)(bp + 8));
            }
        }
        __syncthreads();   // all warps done with buf bb before it is refilled
    }

    float inv0 = 1.0f / l0;
    float inv1 = 1.0f / l1;
    __nv_bfloat16* orow0 = out + ((size_t)(b * SEQ) + q0    ) * DIM + h * HDIM;
    __nv_bfloat16* orow1 = out + ((size_t)(b * SEQ) + q0 + 8) * DIM + h * HDIM;
    #pragma unroll
    for (int dn = 0; dn < 8; dn++) {
        int col = dn * 8 + tig * 2;
        __nv_bfloat162 w0 = __floats2bfloat162_rn(oacc[dn][0] * inv0, oacc[dn][1] * inv0);
        __nv_bfloat162 w1 = __floats2bfloat162_rn(oacc[dn][2] * inv1, oacc[dn][3] * inv1);
        *(uint32_t*)(orow0 + col) = *(uint32_t*)&w0;
        *(uint32_t*)(orow1 + col) = *(uint32_t*)&w1;
    }
}

// ---------------------------------------------------------------------------
// Launcher
// ---------------------------------------------------------------------------
extern "C" void kernel_launch(void* const* d_in, const int* in_sizes, int n_in,
                              void* d_out, int out_size)
{
    const float* x      = (const float*)d_in[0];
    const float* qkv_w  = (const float*)d_in[1];
    const float* qkv_b  = (const float*)d_in[2];
    const float* proj_w = (const float*)d_in[3];
    const float* proj_b = (const float*)d_in[4];
    const float* ff1_w  = (const float*)d_in[5];
    const float* ff1_b  = (const float*)d_in[6];
    const float* ff2_w  = (const float*)d_in[7];
    const float* ff2_b  = (const float*)d_in[8];
    const float* ln1_g  = (const float*)d_in[9];
    const float* ln1_b  = (const float*)d_in[10];
    const float* ln2_g  = (const float*)d_in[11];
    const float* ln2_b  = (const float*)d_in[12];
    float* out = (float*)d_out;

    __nv_bfloat16 *xn, *qkv, *att, *hbuf, *wq, *wp, *w1, *w2;
    float *x1;
    cudaGetSymbolAddress((void**)&xn,   g_xn);
    cudaGetSymbolAddress((void**)&qkv,  g_qkv);
    cudaGetSymbolAddress((void**)&att,  g_att);
    cudaGetSymbolAddress((void**)&x1,   g_x1);
    cudaGetSymbolAddress((void**)&hbuf, g_h);
    cudaGetSymbolAddress((void**)&wq,   g_wq);
    cudaGetSymbolAddress((void**)&wp,   g_wp);
    cudaGetSymbolAddress((void**)&w1,   g_w1);
    cudaGetSymbolAddress((void**)&w2,   g_w2);

    cudaFuncSetAttribute(flash_tc_kernel,
                         cudaFuncAttributeMaxDynamicSharedMemorySize, FTC_SMEM);
    cudaFuncSetAttribute(gemm_bf16_kernel<EPI_BIAS>,
                         cudaFuncAttributeMaxDynamicSharedMemorySize, GEMM_SMEM);
    cudaFuncSetAttribute(gemm_bf16_kernel<EPI_GELU>,
                         cudaFuncAttributeMaxDynamicSharedMemorySize, GEMM_SMEM);
    cudaFuncSetAttribute(gemm_bf16_kernel<EPI_RES>,
                         cudaFuncAttributeMaxDynamicSharedMemorySize, GEMM_SMEM);

    // 0. Convert all weights to bf16 in one launch
    {
        int n0 = QKV_DIM * DIM, n1 = DIM * DIM, n2 = HIDDEN * DIM, n3 = DIM * HIDDEN;
        long total = (long)n0 + n1 + n2 + n3;
        int blocks = (int)((total / 4 + 255) / 256);
        cvt_all_kernel<<<blocks, 256>>>(qkv_w, wq, n0, proj_w, wp, n1,
                                        ff1_w, w1, n2, ff2_w, w2, n3);
    }

    // 1. LN1 -> bf16
    ln_kernel<<<TOKENS, 256>>>(x, ln1_g, ln1_b, xn);

    // 2. QKV projection -> bf16
    {
        dim3 grid(QKV_DIM / 128, TOKENS / 128);
        gemm_bf16_kernel<EPI_BIAS><<<grid, 256, GEMM_SMEM>>>(xn, wq, qkv_b, nullptr, qkv,
                                                             TOKENS, QKV_DIM, DIM);
    }

    // 3. Flash attention -> bf16
    {
        dim3 grid(SEQ / 128, NHEAD, BATCH);
        flash_tc_kernel<<<grid, 256, FTC_SMEM>>>(qkv, att);
    }

    // 4. proj + residual -> fp32 x1
    {
        dim3 grid(DIM / 128, TOKENS / 128);
        gemm_bf16_kernel<EPI_RES><<<grid, 256, GEMM_SMEM>>>(att, wp, proj_b, x, x1,
                                                            TOKENS, DIM, DIM);
    }

    // 5. LN2 -> bf16
    ln_kernel<<<TOKENS, 256>>>(x1, ln2_g, ln2_b, xn);

    // 6. FF1 + GELU -> bf16
    {
        dim3 grid(HIDDEN / 128, TOKENS / 128);
        gemm_bf16_kernel<EPI_GELU><<<grid, 256, GEMM_SMEM>>>(xn, w1, ff1_b, nullptr, hbuf,
                                                             TOKENS, HIDDEN, DIM);
    }

    // 7. FF2 + residual -> fp32 d_out
    {
        dim3 grid(DIM / 128, TOKENS / 128);
        gemm_bf16_kernel<EPI_RES><<<grid, 256, GEMM_SMEM>>>(hbuf, w2, ff2_b, x1, out,
                                                            TOKENS, DIM, HIDDEN);
    }
}